// round 1
// baseline (speedup 1.0000x reference)
#include <cuda_runtime.h>
#include <cstddef>

// Problem dims (fixed by the dataset)
#define INSIZE  2048
#define HSIZE   4096
#define OUTSIZE 2048

// ---------------- device scratch (no allocations allowed) ----------------
__device__ float g_h1[HSIZE];
__device__ float g_m1[HSIZE];
__device__ float g_h2[HSIZE];
__device__ float g_m2[HSIZE];
__device__ float g_Et[(size_t)HSIZE * OUTSIZE];   // 32 MB: Et = W2^T @ (m2 * W3^T)

// ---------------- fp32 GEMV: z = W @ v, optional ReLU mask ----------------
// One block per row, 256 threads, float4 loads, shared reduce.
__global__ void gemv_kernel(const float* __restrict__ W, const float* __restrict__ v,
                            float* __restrict__ h, float* __restrict__ mask, int K)
{
    int row = blockIdx.x;
    const float* w = W + (size_t)row * K;
    float acc = 0.f;
    for (int i = threadIdx.x * 4; i < K; i += blockDim.x * 4) {
        float4 a = *(const float4*)(w + i);
        float4 b = *(const float4*)(v + i);
        acc += a.x * b.x + a.y * b.y + a.z * b.z + a.w * b.w;
    }
    __shared__ float red[256];
    red[threadIdx.x] = acc;
    __syncthreads();
    for (int s = 128; s > 0; s >>= 1) {
        if (threadIdx.x < s) red[threadIdx.x] += red[threadIdx.x + s];
        __syncthreads();
    }
    if (threadIdx.x == 0) {
        float z = red[0];
        if (mask) {
            float m = z > 0.f ? 1.f : 0.f;
            mask[row] = m;
            h[row]    = z * m;
        } else {
            h[row] = z;
        }
    }
}

// ---------------- transpose: in[R,C] -> out[C,R] ----------------
// 32x32 tiles, block (32,8). Dims are multiples of 32.
__global__ void transpose_kernel(const float* __restrict__ in, float* __restrict__ out,
                                 int R, int C)
{
    __shared__ float tile[32][33];
    int x = blockIdx.x * 32 + threadIdx.x;   // col in input
    int y = blockIdx.y * 32 + threadIdx.y;   // row in input
    #pragma unroll
    for (int j = 0; j < 32; j += 8)
        tile[threadIdx.y + j][threadIdx.x] = in[(size_t)(y + j) * C + x];
    __syncthreads();
    int ox = blockIdx.y * 32 + threadIdx.x;  // col in output (= input row)
    int oy = blockIdx.x * 32 + threadIdx.y;  // row in output (= input col)
    #pragma unroll
    for (int j = 0; j < 32; j += 8)
        out[(size_t)(oy + j) * R + ox] = tile[threadIdx.x][threadIdx.y + j];
}

// ---------------- diag fill: out[N,N] = diag(d) (d==nullptr -> identity) ----------------
__global__ void diagfill_kernel(float* __restrict__ out, const float* __restrict__ d, int N)
{
    size_t idx = ((size_t)blockIdx.x * blockDim.x + threadIdx.x) * 4;
    size_t total = (size_t)N * N;
    if (idx >= total) return;
    size_t row = idx / N;
    size_t col = idx - row * N;
    float4 v = make_float4(0.f, 0.f, 0.f, 0.f);
    if (row >= col && row < col + 4) {
        float dv = d ? d[row] : 1.0f;
        ((float*)&v)[row - col] = dv;
    }
    *(float4*)(out + idx) = v;
}

// ---------------- fp32 SGEMM: C[M,N] = A[M,K] @ (scale[k] * B[K,N]) ----------------
// 128x128 block tile, BK=8, 256 threads, 8x8 microtile, float4 global loads.
// M, N multiples of 128; K multiple of 8.
#define BM 128
#define BN 128
#define BK 8
#define TM 8
#define TN 8

__global__ __launch_bounds__(256, 2)
void sgemm_kernel(int M, int N, int K,
                  const float* __restrict__ A, const float* __restrict__ B,
                  const float* __restrict__ scale, float* __restrict__ C)
{
    const int cRow = blockIdx.y;
    const int cCol = blockIdx.x;

    __shared__ float As[BK * BM];
    __shared__ float Bs[BK * BN];

    A += (size_t)cRow * BM * K;
    B += cCol * BN;
    C += (size_t)cRow * BM * N + cCol * BN;

    const int tid       = threadIdx.x;
    const int innerRowA = tid / 2;              // 0..127
    const int innerColA = (tid % 2) * 4;        // 0 or 4
    const int innerRowB = tid / 32;             // 0..7
    const int innerColB = (tid % 32) * 4;       // 0..124
    const int threadRow = tid / 16;             // 0..15
    const int threadCol = tid % 16;             // 0..15

    float acc[TM * TN] = {0.f};
    float regM[TM], regN[TN];

    for (int bk = 0; bk < K; bk += BK) {
        // load A tile (transposed into As[k][m])
        float4 ta = *(const float4*)(&A[(size_t)innerRowA * K + innerColA]);
        As[(innerColA + 0) * BM + innerRowA] = ta.x;
        As[(innerColA + 1) * BM + innerRowA] = ta.y;
        As[(innerColA + 2) * BM + innerRowA] = ta.z;
        As[(innerColA + 3) * BM + innerRowA] = ta.w;
        // load B tile with row scale
        float4 tb = *(const float4*)(&B[(size_t)innerRowB * N + innerColB]);
        float s = scale ? scale[bk + innerRowB] : 1.0f;
        tb.x *= s; tb.y *= s; tb.z *= s; tb.w *= s;
        *(float4*)(&Bs[innerRowB * BN + innerColB]) = tb;
        __syncthreads();

        A += BK;
        B += (size_t)BK * N;

        #pragma unroll
        for (int k = 0; k < BK; k++) {
            #pragma unroll
            for (int i = 0; i < TM; i++) regM[i] = As[k * BM + threadRow * TM + i];
            #pragma unroll
            for (int j = 0; j < TN; j++) regN[j] = Bs[k * BN + threadCol * TN + j];
            #pragma unroll
            for (int i = 0; i < TM; i++)
                #pragma unroll
                for (int j = 0; j < TN; j++)
                    acc[i * TN + j] += regM[i] * regN[j];
        }
        __syncthreads();
    }

    #pragma unroll
    for (int i = 0; i < TM; i++) {
        #pragma unroll
        for (int j = 0; j < TN; j += 4) {
            float4 v = make_float4(acc[i * TN + j],     acc[i * TN + j + 1],
                                   acc[i * TN + j + 2], acc[i * TN + j + 3]);
            *(float4*)(&C[(size_t)(threadRow * TM + i) * N + threadCol * TN + j]) = v;
        }
    }
}

// ---------------- launch ----------------
extern "C" void kernel_launch(void* const* d_in, const int* in_sizes, int n_in,
                              void* d_out, int out_size)
{
    (void)in_sizes; (void)n_in; (void)out_size;
    const float* x  = (const float*)d_in[0];
    const float* W1 = (const float*)d_in[1];   // [4096, 2048]
    const float* W2 = (const float*)d_in[2];   // [4096, 4096]
    const float* W3 = (const float*)d_in[3];   // [2048, 4096]
    float* out = (float*)d_out;

    float *h1, *m1, *h2, *m2, *Et;
    cudaGetSymbolAddress((void**)&h1, g_h1);
    cudaGetSymbolAddress((void**)&m1, g_m1);
    cudaGetSymbolAddress((void**)&h2, g_h2);
    cudaGetSymbolAddress((void**)&m2, g_m2);
    cudaGetSymbolAddress((void**)&Et, g_Et);

    // Output offsets (floats)
    const size_t OFF_OUT = 0;                                        // [1, 2048]
    const size_t OFF_DJM = OFF_OUT + OUTSIZE;                        // [2048, 2048]
    const size_t OFF_J1  = OFF_DJM + (size_t)INSIZE * OUTSIZE;       // W1^T [2048, 4096]
    const size_t OFF_J2  = OFF_J1  + (size_t)INSIZE * HSIZE;         // diag(m1) [4096, 4096]
    const size_t OFF_J3  = OFF_J2  + (size_t)HSIZE * HSIZE;          // W2^T [4096, 4096]
    const size_t OFF_J4  = OFF_J3  + (size_t)HSIZE * HSIZE;          // diag(m2) [4096, 4096]
    const size_t OFF_J5  = OFF_J4  + (size_t)HSIZE * HSIZE;          // W3^T [4096, 2048]
    const size_t OFF_J6  = OFF_J5  + (size_t)HSIZE * OUTSIZE;        // eye [2048, 2048]

    // Forward pass (fp32 GEMVs; exact-ish masks matter for correctness)
    gemv_kernel<<<HSIZE,   256>>>(W1, x,  h1, m1, INSIZE);
    gemv_kernel<<<HSIZE,   256>>>(W2, h1, h2, m2, HSIZE);
    gemv_kernel<<<OUTSIZE, 256>>>(W3, h2, out + OFF_OUT, nullptr, HSIZE);

    // Jacobian copies (transposes written into their output slots, reused by GEMMs)
    {
        dim3 blk(32, 8);
        transpose_kernel<<<dim3(INSIZE/32, HSIZE/32), blk>>>(W1, out + OFF_J1, HSIZE, INSIZE);  // [2048,4096]
        transpose_kernel<<<dim3(HSIZE/32,  HSIZE/32), blk>>>(W2, out + OFF_J3, HSIZE, HSIZE);   // [4096,4096]
        transpose_kernel<<<dim3(HSIZE/32,  OUTSIZE/32), blk>>>(W3, out + OFF_J5, OUTSIZE, HSIZE); // [4096,2048]
    }
    {
        size_t nH = ((size_t)HSIZE * HSIZE) / 4;
        size_t nO = ((size_t)OUTSIZE * OUTSIZE) / 4;
        diagfill_kernel<<<(unsigned)((nH + 255) / 256), 256>>>(out + OFF_J2, m1, HSIZE);
        diagfill_kernel<<<(unsigned)((nH + 255) / 256), 256>>>(out + OFF_J4, m2, HSIZE);
        diagfill_kernel<<<(unsigned)((nO + 255) / 256), 256>>>(out + OFF_J6, nullptr, OUTSIZE);
    }

    // DJM = W1^T @ diag(m1) @ W2^T @ diag(m2) @ W3^T
    // GEMM1: Et[4096,2048] = W2^T @ (m2 * W3^T)   (reads jac slots written above)
    sgemm_kernel<<<dim3(OUTSIZE / BN, HSIZE / BM), 256>>>(
        HSIZE, OUTSIZE, HSIZE, out + OFF_J3, out + OFF_J5, m2, Et);
    // GEMM2: DJM[2048,2048] = W1^T @ (m1 * Et)
    sgemm_kernel<<<dim3(OUTSIZE / BN, INSIZE / BM), 256>>>(
        INSIZE, OUTSIZE, HSIZE, out + OFF_J1, Et, m1, out + OFF_DJM);
}

// round 2
// speedup vs baseline: 3.0509x; 3.0509x over previous
#include <cuda_runtime.h>
#include <cstddef>

// Problem dims (fixed by the dataset)
#define INSIZE  2048
#define HSIZE   4096
#define OUTSIZE 2048

// ---------------- device scratch (no allocations allowed) ----------------
__device__ float g_h1[HSIZE];
__device__ float g_m1[HSIZE];
__device__ float g_h2[HSIZE];
__device__ float g_m2[HSIZE];
__device__ float g_Et[(size_t)HSIZE * OUTSIZE];   // 32 MB: Et = W2^T @ (m2 * W3^T)

// ---------------- fp32 GEMV: z = W @ v, optional ReLU mask ----------------
__global__ void gemv_kernel(const float* __restrict__ W, const float* __restrict__ v,
                            float* __restrict__ h, float* __restrict__ mask, int K)
{
    int row = blockIdx.x;
    const float* w = W + (size_t)row * K;
    float acc = 0.f;
    for (int i = threadIdx.x * 4; i < K; i += blockDim.x * 4) {
        float4 a = *(const float4*)(w + i);
        float4 b = *(const float4*)(v + i);
        acc += a.x * b.x + a.y * b.y + a.z * b.z + a.w * b.w;
    }
    __shared__ float red[256];
    red[threadIdx.x] = acc;
    __syncthreads();
    for (int s = 128; s > 0; s >>= 1) {
        if (threadIdx.x < s) red[threadIdx.x] += red[threadIdx.x + s];
        __syncthreads();
    }
    if (threadIdx.x == 0) {
        float z = red[0];
        if (mask) {
            float m = z > 0.f ? 1.f : 0.f;
            mask[row] = m;
            h[row]    = z * m;
        } else {
            h[row] = z;
        }
    }
}

// ---------------- transpose: in[R,C] -> out[C,R] ----------------
__global__ void transpose_kernel(const float* __restrict__ in, float* __restrict__ out,
                                 int R, int C)
{
    __shared__ float tile[32][33];
    int x = blockIdx.x * 32 + threadIdx.x;
    int y = blockIdx.y * 32 + threadIdx.y;
    #pragma unroll
    for (int j = 0; j < 32; j += 8)
        tile[threadIdx.y + j][threadIdx.x] = in[(size_t)(y + j) * C + x];
    __syncthreads();
    int ox = blockIdx.y * 32 + threadIdx.x;
    int oy = blockIdx.x * 32 + threadIdx.y;
    #pragma unroll
    for (int j = 0; j < 32; j += 8)
        out[(size_t)(oy + j) * R + ox] = tile[threadIdx.x][threadIdx.y + j];
}

// ---------------- diag fill: out[N,N] = diag(d) (d==nullptr -> identity) ----------------
__global__ void diagfill_kernel(float* __restrict__ out, const float* __restrict__ d, int N)
{
    size_t idx = ((size_t)blockIdx.x * blockDim.x + threadIdx.x) * 4;
    size_t total = (size_t)N * N;
    if (idx >= total) return;
    size_t row = idx / N;
    size_t col = idx - row * N;
    float4 v = make_float4(0.f, 0.f, 0.f, 0.f);
    if (row >= col && row < col + 4) {
        float dv = d ? d[row] : 1.0f;
        ((float*)&v)[row - col] = dv;
    }
    *(float4*)(out + idx) = v;
}

// ---------------- tf32 tensor-core GEMM ----------------
// C[M,N] = A[M,K] @ (scale[k] * B[K,N]), row-major, fp32 in/out, tf32 mma.
// Block tile 128x128x32, 8 warps, each warp 32x64 via m16n8k8 fragments.
#define BM  128
#define BN  128
#define BKT 32
#define ASTR 36    // As[m][k], stride 36 -> frag addr = 4g+t mod 32 (conflict-free)
#define BSTR 136   // Bs[k][n], stride 136 -> frag addr = 8t+g mod 32 (conflict-free)

__device__ __forceinline__ unsigned f2tf32(float f) {
    unsigned r;
    asm volatile("cvt.rna.tf32.f32 %0, %1;" : "=r"(r) : "f"(f));
    return r;
}

__global__ __launch_bounds__(256)
void tf32gemm_kernel(int M, int N, int K,
                     const float* __restrict__ A, const float* __restrict__ B,
                     const float* __restrict__ scale, float* __restrict__ C)
{
    __shared__ unsigned As[BM * ASTR];
    __shared__ unsigned Bs[BKT * BSTR];

    const int tid  = threadIdx.x;
    const int wid  = tid / 32;
    const int lane = tid % 32;
    const int g    = lane >> 2;   // group-of-4 id (0..7)
    const int t    = lane & 3;    // thread-in-group (0..3)

    const int warpM = wid % 4;    // 4 warps along M -> 32 rows each
    const int warpN = wid / 4;    // 2 warps along N -> 64 cols each

    const size_t aBase = (size_t)blockIdx.y * BM * K;
    const size_t cBase = (size_t)blockIdx.y * BM * N + blockIdx.x * BN;
    const int    bCol  = blockIdx.x * BN;

    // global-load coords
    const int arow = tid / 8;           // 0..31 (stride 32 over 128 rows)
    const int acol = (tid % 8) * 4;     // 0..28
    const int brow = tid / 32;          // 0..7  (stride 8 over 32 rows)
    const int bcol = (tid % 32) * 4;    // 0..124

    float acc[2][8][4];
    #pragma unroll
    for (int i = 0; i < 2; i++)
        #pragma unroll
        for (int j = 0; j < 8; j++)
            #pragma unroll
            for (int q = 0; q < 4; q++) acc[i][j][q] = 0.f;

    for (int bk = 0; bk < K; bk += BKT) {
        // load A tile: 128x32, each thread 4 float4s
        #pragma unroll
        for (int r = 0; r < 4; r++) {
            int row = arow + r * 32;
            float4 v = *(const float4*)(&A[aBase + (size_t)row * K + bk + acol]);
            unsigned* dst = &As[row * ASTR + acol];
            dst[0] = f2tf32(v.x); dst[1] = f2tf32(v.y);
            dst[2] = f2tf32(v.z); dst[3] = f2tf32(v.w);
        }
        // load B tile: 32x128, each thread 4 float4s, apply row scale
        #pragma unroll
        for (int r = 0; r < 4; r++) {
            int row = brow + r * 8;
            float4 v = *(const float4*)(&B[(size_t)(bk + row) * N + bCol + bcol]);
            float s = scale ? scale[bk + row] : 1.0f;
            unsigned* dst = &Bs[row * BSTR + bcol];
            dst[0] = f2tf32(v.x * s); dst[1] = f2tf32(v.y * s);
            dst[2] = f2tf32(v.z * s); dst[3] = f2tf32(v.w * s);
        }
        __syncthreads();

        #pragma unroll
        for (int kk = 0; kk < BKT; kk += 8) {
            // A fragments: 2 m16 tiles
            unsigned a[2][4];
            #pragma unroll
            for (int i = 0; i < 2; i++) {
                int mb = warpM * 32 + i * 16;
                a[i][0] = As[(mb + g)     * ASTR + kk + t];
                a[i][1] = As[(mb + g + 8) * ASTR + kk + t];
                a[i][2] = As[(mb + g)     * ASTR + kk + t + 4];
                a[i][3] = As[(mb + g + 8) * ASTR + kk + t + 4];
            }
            // B fragments: 8 n8 tiles
            unsigned b[8][2];
            #pragma unroll
            for (int j = 0; j < 8; j++) {
                int nb = warpN * 64 + j * 8;
                b[j][0] = Bs[(kk + t)     * BSTR + nb + g];
                b[j][1] = Bs[(kk + t + 4) * BSTR + nb + g];
            }
            #pragma unroll
            for (int i = 0; i < 2; i++)
                #pragma unroll
                for (int j = 0; j < 8; j++) {
                    asm volatile(
                        "mma.sync.aligned.m16n8k8.row.col.f32.tf32.tf32.f32 "
                        "{%0,%1,%2,%3}, {%4,%5,%6,%7}, {%8,%9}, {%0,%1,%2,%3};"
                        : "+f"(acc[i][j][0]), "+f"(acc[i][j][1]),
                          "+f"(acc[i][j][2]), "+f"(acc[i][j][3])
                        : "r"(a[i][0]), "r"(a[i][1]), "r"(a[i][2]), "r"(a[i][3]),
                          "r"(b[j][0]), "r"(b[j][1]));
                }
        }
        __syncthreads();
    }

    // epilogue: c0,c1 at (g, 2t), c2,c3 at (g+8, 2t)
    #pragma unroll
    for (int i = 0; i < 2; i++) {
        int row0 = warpM * 32 + i * 16 + g;
        #pragma unroll
        for (int j = 0; j < 8; j++) {
            int col = warpN * 64 + j * 8 + t * 2;
            *(float2*)(&C[cBase + (size_t)row0 * N + col]) =
                make_float2(acc[i][j][0], acc[i][j][1]);
            *(float2*)(&C[cBase + (size_t)(row0 + 8) * N + col]) =
                make_float2(acc[i][j][2], acc[i][j][3]);
        }
    }
}

// ---------------- launch ----------------
extern "C" void kernel_launch(void* const* d_in, const int* in_sizes, int n_in,
                              void* d_out, int out_size)
{
    (void)in_sizes; (void)n_in; (void)out_size;
    const float* x  = (const float*)d_in[0];
    const float* W1 = (const float*)d_in[1];   // [4096, 2048]
    const float* W2 = (const float*)d_in[2];   // [4096, 4096]
    const float* W3 = (const float*)d_in[3];   // [2048, 4096]
    float* out = (float*)d_out;

    float *h1, *m1, *h2, *m2, *Et;
    cudaGetSymbolAddress((void**)&h1, g_h1);
    cudaGetSymbolAddress((void**)&m1, g_m1);
    cudaGetSymbolAddress((void**)&h2, g_h2);
    cudaGetSymbolAddress((void**)&m2, g_m2);
    cudaGetSymbolAddress((void**)&Et, g_Et);

    // Output offsets (floats)
    const size_t OFF_OUT = 0;                                        // [1, 2048]
    const size_t OFF_DJM = OFF_OUT + OUTSIZE;                        // [2048, 2048]
    const size_t OFF_J1  = OFF_DJM + (size_t)INSIZE * OUTSIZE;       // W1^T [2048, 4096]
    const size_t OFF_J2  = OFF_J1  + (size_t)INSIZE * HSIZE;         // diag(m1) [4096, 4096]
    const size_t OFF_J3  = OFF_J2  + (size_t)HSIZE * HSIZE;          // W2^T [4096, 4096]
    const size_t OFF_J4  = OFF_J3  + (size_t)HSIZE * HSIZE;          // diag(m2) [4096, 4096]
    const size_t OFF_J5  = OFF_J4  + (size_t)HSIZE * HSIZE;          // W3^T [4096, 2048]
    const size_t OFF_J6  = OFF_J5  + (size_t)HSIZE * OUTSIZE;        // eye [2048, 2048]

    // Forward pass (fp32 GEMVs; exact masks matter for correctness)
    gemv_kernel<<<HSIZE,   256>>>(W1, x,  h1, m1, INSIZE);
    gemv_kernel<<<HSIZE,   256>>>(W2, h1, h2, m2, HSIZE);
    gemv_kernel<<<OUTSIZE, 256>>>(W3, h2, out + OFF_OUT, nullptr, HSIZE);

    // Jacobian copies (transposes written into their output slots, reused by GEMMs)
    {
        dim3 blk(32, 8);
        transpose_kernel<<<dim3(INSIZE/32, HSIZE/32), blk>>>(W1, out + OFF_J1, HSIZE, INSIZE);
        transpose_kernel<<<dim3(HSIZE/32,  HSIZE/32), blk>>>(W2, out + OFF_J3, HSIZE, HSIZE);
        transpose_kernel<<<dim3(HSIZE/32,  OUTSIZE/32), blk>>>(W3, out + OFF_J5, OUTSIZE, HSIZE);
    }
    {
        size_t nH = ((size_t)HSIZE * HSIZE) / 4;
        size_t nO = ((size_t)OUTSIZE * OUTSIZE) / 4;
        diagfill_kernel<<<(unsigned)((nH + 255) / 256), 256>>>(out + OFF_J2, m1, HSIZE);
        diagfill_kernel<<<(unsigned)((nH + 255) / 256), 256>>>(out + OFF_J4, m2, HSIZE);
        diagfill_kernel<<<(unsigned)((nO + 255) / 256), 256>>>(out + OFF_J6, nullptr, OUTSIZE);
    }

    // DJM = W1^T @ diag(m1) @ W2^T @ diag(m2) @ W3^T   (tensor-core tf32 GEMMs)
    // GEMM1: Et[4096,2048] = W2^T @ (m2 * W3^T)
    tf32gemm_kernel<<<dim3(OUTSIZE / BN, HSIZE / BM), 256>>>(
        HSIZE, OUTSIZE, HSIZE, out + OFF_J3, out + OFF_J5, m2, Et);
    // GEMM2: DJM[2048,2048] = W1^T @ (m1 * Et)
    tf32gemm_kernel<<<dim3(OUTSIZE / BN, INSIZE / BM), 256>>>(
        INSIZE, OUTSIZE, HSIZE, out + OFF_J1, Et, m1, out + OFF_DJM);
}

// round 3
// speedup vs baseline: 6.8129x; 2.2331x over previous
#include <cuda_runtime.h>
#include <cstddef>

// Problem dims (fixed by the dataset)
#define INSIZE  2048
#define HSIZE   4096
#define OUTSIZE 2048

// ---------------- device scratch (no allocations allowed) ----------------
__device__ float g_h1[HSIZE];
__device__ float g_m1[HSIZE];
__device__ float g_h2[HSIZE];
__device__ float g_m2[HSIZE];
__device__ float g_Et[(size_t)HSIZE * OUTSIZE];            // compacted Et rows
__device__ float g_A1[(size_t)HSIZE * HSIZE];              // W2^T[idx1][idx2], worst case 64MB
__device__ float g_A2[(size_t)INSIZE * HSIZE];             // W1^T[:, idx1], worst case 32MB
__device__ float g_B1[(size_t)HSIZE * OUTSIZE];            // W3^T rows idx2, worst case 32MB
__device__ int   g_idx1[HSIZE];
__device__ int   g_idx2[HSIZE];
__device__ int   g_cnt1[2];   // [raw, padded-to-32]
__device__ int   g_cnt2[2];
__device__ int   g_c2048[2] = {INSIZE, INSIZE};            // static M-limit for GEMM2

// ---------------- fp32 GEMV: z = W @ v, optional ReLU mask ----------------
__global__ void gemv_kernel(const float* __restrict__ W, const float* __restrict__ v,
                            float* __restrict__ h, float* __restrict__ mask, int K)
{
    int row = blockIdx.x;
    const float* w = W + (size_t)row * K;
    float acc = 0.f;
    for (int i = threadIdx.x * 4; i < K; i += blockDim.x * 4) {
        float4 a = *(const float4*)(w + i);
        float4 b = *(const float4*)(v + i);
        acc += a.x * b.x + a.y * b.y + a.z * b.z + a.w * b.w;
    }
    __shared__ float red[256];
    red[threadIdx.x] = acc;
    __syncthreads();
    for (int s = 128; s > 0; s >>= 1) {
        if (threadIdx.x < s) red[threadIdx.x] += red[threadIdx.x + s];
        __syncthreads();
    }
    if (threadIdx.x == 0) {
        float z = red[0];
        if (mask) {
            float m = z > 0.f ? 1.f : 0.f;
            mask[row] = m;
            h[row]    = z * m;
        } else {
            h[row] = z;
        }
    }
}

// ---------------- transpose: in[R,C] -> out[C,R] ----------------
__global__ void transpose_kernel(const float* __restrict__ in, float* __restrict__ out,
                                 int R, int C)
{
    __shared__ float tile[32][33];
    int x = blockIdx.x * 32 + threadIdx.x;
    int y = blockIdx.y * 32 + threadIdx.y;
    #pragma unroll
    for (int j = 0; j < 32; j += 8)
        tile[threadIdx.y + j][threadIdx.x] = in[(size_t)(y + j) * C + x];
    __syncthreads();
    int ox = blockIdx.y * 32 + threadIdx.x;
    int oy = blockIdx.x * 32 + threadIdx.y;
    #pragma unroll
    for (int j = 0; j < 32; j += 8)
        out[(size_t)(oy + j) * R + ox] = tile[threadIdx.x][threadIdx.y + j];
}

// ---------------- diag fill: out[N,N] = diag(d) (d==nullptr -> identity) ----------------
__global__ void diagfill_kernel(float* __restrict__ out, const float* __restrict__ d, int N)
{
    size_t idx = ((size_t)blockIdx.x * blockDim.x + threadIdx.x) * 4;
    size_t total = (size_t)N * N;
    if (idx >= total) return;
    size_t row = idx / N;
    size_t col = idx - row * N;
    float4 v = make_float4(0.f, 0.f, 0.f, 0.f);
    if (row >= col && row < col + 4) {
        float dv = d ? d[row] : 1.0f;
        ((float*)&v)[row - col] = dv;
    }
    *(float4*)(out + idx) = v;
}

// ---------------- build sorted index list of nonzero mask entries ----------------
// Single block, 1024 threads, Hillis-Steele block scan per 1024-chunk.
__global__ void build_idx_kernel(const float* __restrict__ mask, int n,
                                 int* __restrict__ idx, int* __restrict__ cnt)
{
    __shared__ int sdata[1024];
    __shared__ int sbase;
    int tid = threadIdx.x;
    if (tid == 0) sbase = 0;
    __syncthreads();
    for (int chunk = 0; chunk < n; chunk += 1024) {
        int i = chunk + tid;
        int flag = (i < n && mask[i] != 0.f) ? 1 : 0;
        sdata[tid] = flag;
        __syncthreads();
        #pragma unroll
        for (int off = 1; off < 1024; off <<= 1) {
            int v = (tid >= off) ? sdata[tid - off] : 0;
            __syncthreads();
            sdata[tid] += v;
            __syncthreads();
        }
        int incl  = sdata[tid];
        int total = sdata[1023];
        if (flag) idx[sbase + incl - 1] = i;
        __syncthreads();
        if (tid == 0) sbase += total;
        __syncthreads();
    }
    if (tid == 0) {
        cnt[0] = sbase;
        cnt[1] = (sbase + 31) & ~31;
    }
}

// ---------------- gather kernels (pad regions filled with exact zeros) ----------------
// out[r, j] = (r<rcnt && j<ccnt) ? src[ridx[r]*sld + cidx[j]] : 0 ; out ld = ccnt_pad
__global__ void gatherRC_kernel(const float* __restrict__ src, int sld,
                                const int* __restrict__ ridx, const int* __restrict__ cidx,
                                const int* __restrict__ cntr, const int* __restrict__ cntc,
                                float* __restrict__ out)
{
    int r = blockIdx.x;
    int rc = cntr[0], rp = cntr[1];
    int cc = cntc[0], cp = cntc[1];
    if (r >= rp) return;
    bool ok = (r < rc);
    const float* s = src + (size_t)(ok ? ridx[r] : 0) * sld;
    float* o = out + (size_t)r * cp;
    for (int j = threadIdx.x; j < cp; j += blockDim.x)
        o[j] = (ok && j < cc) ? s[cidx[j]] : 0.f;
}

// out[r, j] = (j<ccnt) ? src[r*sld + cidx[j]] : 0 ; all rows; out ld = ccnt_pad
__global__ void gatherC_kernel(const float* __restrict__ src, int sld,
                               const int* __restrict__ cidx, const int* __restrict__ cntc,
                               float* __restrict__ out)
{
    int r = blockIdx.x;
    int cc = cntc[0], cp = cntc[1];
    const float* s = src + (size_t)r * sld;
    float* o = out + (size_t)r * cp;
    for (int j = threadIdx.x; j < cp; j += blockDim.x)
        o[j] = (j < cc) ? s[cidx[j]] : 0.f;
}

// out[r, :] = (r<rcnt) ? src[ridx[r], :] : 0 ; out ld = ncols
__global__ void gatherR_kernel(const float* __restrict__ src, int sld,
                               const int* __restrict__ ridx, const int* __restrict__ cntr,
                               float* __restrict__ out, int ncols)
{
    int r = blockIdx.x;
    int rc = cntr[0], rp = cntr[1];
    if (r >= rp) return;
    bool ok = (r < rc);
    const float* s = src + (size_t)(ok ? ridx[r] : 0) * sld;
    float* o = out + (size_t)r * ncols;
    for (int j = threadIdx.x * 4; j < ncols; j += blockDim.x * 4) {
        float4 v = ok ? *(const float4*)(s + j) : make_float4(0.f, 0.f, 0.f, 0.f);
        *(float4*)(o + j) = v;
    }
}

// ---------------- tf32 tensor-core GEMM, dynamic K / M-limit from device ----------------
// C[M,N] = A[M,K] @ B[K,N]; K = kp[1] (multiple of 32), blocks with row-base >= mp[1] exit.
// N fixed = 2048. Block tile 128x128x32, 8 warps, warp 32x64 via m16n8k8.
#define BM  128
#define BN  128
#define BKT 32
#define NDIM 2048
#define ASTR 36
#define BSTR 136

__device__ __forceinline__ unsigned f2tf32(float f) {
    unsigned r;
    asm volatile("cvt.rna.tf32.f32 %0, %1;" : "=r"(r) : "f"(f));
    return r;
}

__global__ __launch_bounds__(256)
void tf32gemm_kernel(const int* __restrict__ kp, const int* __restrict__ mp,
                     const float* __restrict__ A, const float* __restrict__ B,
                     float* __restrict__ C)
{
    if ((int)(blockIdx.y * BM) >= mp[1]) return;
    const int K = kp[1];

    __shared__ unsigned As[BM * ASTR];
    __shared__ unsigned Bs[BKT * BSTR];

    const int tid  = threadIdx.x;
    const int wid  = tid / 32;
    const int lane = tid % 32;
    const int g    = lane >> 2;
    const int t    = lane & 3;

    const int warpM = wid % 4;
    const int warpN = wid / 4;

    const size_t aBase = (size_t)blockIdx.y * BM * K;
    const size_t cBase = (size_t)blockIdx.y * BM * NDIM + blockIdx.x * BN;
    const int    bCol  = blockIdx.x * BN;

    const int arow = tid / 8;
    const int acol = (tid % 8) * 4;
    const int brow = tid / 32;
    const int bcol = (tid % 32) * 4;

    float acc[2][8][4];
    #pragma unroll
    for (int i = 0; i < 2; i++)
        #pragma unroll
        for (int j = 0; j < 8; j++)
            #pragma unroll
            for (int q = 0; q < 4; q++) acc[i][j][q] = 0.f;

    for (int bk = 0; bk < K; bk += BKT) {
        #pragma unroll
        for (int r = 0; r < 4; r++) {
            int row = arow + r * 32;
            float4 v = *(const float4*)(&A[aBase + (size_t)row * K + bk + acol]);
            unsigned* dst = &As[row * ASTR + acol];
            dst[0] = f2tf32(v.x); dst[1] = f2tf32(v.y);
            dst[2] = f2tf32(v.z); dst[3] = f2tf32(v.w);
        }
        #pragma unroll
        for (int r = 0; r < 4; r++) {
            int row = brow + r * 8;
            float4 v = *(const float4*)(&B[(size_t)(bk + row) * NDIM + bCol + bcol]);
            unsigned* dst = &Bs[row * BSTR + bcol];
            dst[0] = f2tf32(v.x); dst[1] = f2tf32(v.y);
            dst[2] = f2tf32(v.z); dst[3] = f2tf32(v.w);
        }
        __syncthreads();

        #pragma unroll
        for (int kk = 0; kk < BKT; kk += 8) {
            unsigned a[2][4];
            #pragma unroll
            for (int i = 0; i < 2; i++) {
                int mb = warpM * 32 + i * 16;
                a[i][0] = As[(mb + g)     * ASTR + kk + t];
                a[i][1] = As[(mb + g + 8) * ASTR + kk + t];
                a[i][2] = As[(mb + g)     * ASTR + kk + t + 4];
                a[i][3] = As[(mb + g + 8) * ASTR + kk + t + 4];
            }
            unsigned b[8][2];
            #pragma unroll
            for (int j = 0; j < 8; j++) {
                int nb = warpN * 64 + j * 8;
                b[j][0] = Bs[(kk + t)     * BSTR + nb + g];
                b[j][1] = Bs[(kk + t + 4) * BSTR + nb + g];
            }
            #pragma unroll
            for (int i = 0; i < 2; i++)
                #pragma unroll
                for (int j = 0; j < 8; j++) {
                    asm volatile(
                        "mma.sync.aligned.m16n8k8.row.col.f32.tf32.tf32.f32 "
                        "{%0,%1,%2,%3}, {%4,%5,%6,%7}, {%8,%9}, {%0,%1,%2,%3};"
                        : "+f"(acc[i][j][0]), "+f"(acc[i][j][1]),
                          "+f"(acc[i][j][2]), "+f"(acc[i][j][3])
                        : "r"(a[i][0]), "r"(a[i][1]), "r"(a[i][2]), "r"(a[i][3]),
                          "r"(b[j][0]), "r"(b[j][1]));
                }
        }
        __syncthreads();
    }

    #pragma unroll
    for (int i = 0; i < 2; i++) {
        int row0 = warpM * 32 + i * 16 + g;
        #pragma unroll
        for (int j = 0; j < 8; j++) {
            int col = warpN * 64 + j * 8 + t * 2;
            *(float2*)(&C[cBase + (size_t)row0 * NDIM + col]) =
                make_float2(acc[i][j][0], acc[i][j][1]);
            *(float2*)(&C[cBase + (size_t)(row0 + 8) * NDIM + col]) =
                make_float2(acc[i][j][2], acc[i][j][3]);
        }
    }
}

// ---------------- launch ----------------
extern "C" void kernel_launch(void* const* d_in, const int* in_sizes, int n_in,
                              void* d_out, int out_size)
{
    (void)in_sizes; (void)n_in; (void)out_size;
    const float* x  = (const float*)d_in[0];
    const float* W1 = (const float*)d_in[1];   // [4096, 2048]
    const float* W2 = (const float*)d_in[2];   // [4096, 4096]
    const float* W3 = (const float*)d_in[3];   // [2048, 4096]
    float* out = (float*)d_out;

    float *h1, *m1, *h2, *m2, *Et, *A1, *A2, *B1;
    int *idx1, *idx2, *cnt1, *cnt2, *c2048;
    cudaGetSymbolAddress((void**)&h1, g_h1);
    cudaGetSymbolAddress((void**)&m1, g_m1);
    cudaGetSymbolAddress((void**)&h2, g_h2);
    cudaGetSymbolAddress((void**)&m2, g_m2);
    cudaGetSymbolAddress((void**)&Et, g_Et);
    cudaGetSymbolAddress((void**)&A1, g_A1);
    cudaGetSymbolAddress((void**)&A2, g_A2);
    cudaGetSymbolAddress((void**)&B1, g_B1);
    cudaGetSymbolAddress((void**)&idx1, g_idx1);
    cudaGetSymbolAddress((void**)&idx2, g_idx2);
    cudaGetSymbolAddress((void**)&cnt1, g_cnt1);
    cudaGetSymbolAddress((void**)&cnt2, g_cnt2);
    cudaGetSymbolAddress((void**)&c2048, g_c2048);

    // Output offsets (floats)
    const size_t OFF_OUT = 0;                                        // [1, 2048]
    const size_t OFF_DJM = OFF_OUT + OUTSIZE;                        // [2048, 2048]
    const size_t OFF_J1  = OFF_DJM + (size_t)INSIZE * OUTSIZE;       // W1^T [2048, 4096]
    const size_t OFF_J2  = OFF_J1  + (size_t)INSIZE * HSIZE;         // diag(m1) [4096, 4096]
    const size_t OFF_J3  = OFF_J2  + (size_t)HSIZE * HSIZE;          // W2^T [4096, 4096]
    const size_t OFF_J4  = OFF_J3  + (size_t)HSIZE * HSIZE;          // diag(m2) [4096, 4096]
    const size_t OFF_J5  = OFF_J4  + (size_t)HSIZE * HSIZE;          // W3^T [4096, 2048]
    const size_t OFF_J6  = OFF_J5  + (size_t)HSIZE * OUTSIZE;        // eye [2048, 2048]

    // Forward pass (fp32 GEMVs; exact masks matter for correctness)
    gemv_kernel<<<HSIZE,   256>>>(W1, x,  h1, m1, INSIZE);
    gemv_kernel<<<HSIZE,   256>>>(W2, h1, h2, m2, HSIZE);
    gemv_kernel<<<OUTSIZE, 256>>>(W3, h2, out + OFF_OUT, nullptr, HSIZE);

    // Jacobian transposes into output slots (reused as GEMM/gather sources)
    {
        dim3 blk(32, 8);
        transpose_kernel<<<dim3(INSIZE/32, HSIZE/32), blk>>>(W1, out + OFF_J1, HSIZE, INSIZE);
        transpose_kernel<<<dim3(HSIZE/32,  HSIZE/32), blk>>>(W2, out + OFF_J3, HSIZE, HSIZE);
        transpose_kernel<<<dim3(HSIZE/32,  OUTSIZE/32), blk>>>(W3, out + OFF_J5, OUTSIZE, HSIZE);
    }
    {
        size_t nH = ((size_t)HSIZE * HSIZE) / 4;
        size_t nO = ((size_t)OUTSIZE * OUTSIZE) / 4;
        diagfill_kernel<<<(unsigned)((nH + 255) / 256), 256>>>(out + OFF_J2, m1, HSIZE);
        diagfill_kernel<<<(unsigned)((nH + 255) / 256), 256>>>(out + OFF_J4, m2, HSIZE);
        diagfill_kernel<<<(unsigned)((nO + 255) / 256), 256>>>(out + OFF_J6, nullptr, OUTSIZE);
    }

    // Sparsity compaction: ReLU masks kill ~half the rows/cols of the chain.
    build_idx_kernel<<<1, 1024>>>(m1, HSIZE, idx1, cnt1);
    build_idx_kernel<<<1, 1024>>>(m2, HSIZE, idx2, cnt2);
    // A1[n1p, n2p] = W2^T[idx1, idx2]
    gatherRC_kernel<<<HSIZE, 256>>>(out + OFF_J3, HSIZE, idx1, idx2, cnt1, cnt2, A1);
    // B1[n2p, 2048] = W3^T[idx2, :]
    gatherR_kernel<<<HSIZE, 256>>>(out + OFF_J5, OUTSIZE, idx2, cnt2, B1, OUTSIZE);
    // A2[2048, n1p] = W1^T[:, idx1]
    gatherC_kernel<<<INSIZE, 256>>>(out + OFF_J1, HSIZE, idx1, cnt1, A2);

    // GEMM1: Et[n1p, 2048] = A1 @ B1   (K = n2p, M-limit = n1p)
    tf32gemm_kernel<<<dim3(NDIM / BN, HSIZE / BM), 256>>>(cnt2, cnt1, A1, B1, Et);
    // GEMM2: DJM[2048, 2048] = A2 @ Et (K = n1p)
    tf32gemm_kernel<<<dim3(NDIM / BN, INSIZE / BM), 256>>>(cnt1, c2048, A2, Et, out + OFF_DJM);
}